// round 1
// baseline (speedup 1.0000x reference)
#include <cuda_runtime.h>

// Problem sizes (fixed by the reference)
#define NB 32
#define NL 1024
#define NC 64
#define NROWS (NB * NL)          // 32768
#define BN_EPS 1e-5f

// ---------------- scratch (device globals; no allocations allowed) ----------
__device__ float g_psum[256 * 64];
__device__ float g_psq[256 * 64];
__device__ float g_Wp[64 * 64];       // scale-folded weight
__device__ float g_bp[64];            // shift-folded bias
__device__ float g_sqd[NROWS];        // sqrt(degree)
__device__ float g_rsd[NROWS];        // rsqrt(degree)
__device__ float g_Y[NROWS * 64];     // Y = rsqrt(d) * (Hn @ W + b), 8 MB

// ---------------- packed f32x2 helpers (FFMA2: 2x fp32 throughput) ----------
__device__ __forceinline__ unsigned long long pack2(float a) {
    unsigned long long r;
    asm("mov.b64 %0, {%1, %1};" : "=l"(r) : "f"(a));
    return r;
}
__device__ __forceinline__ void ffma2(unsigned long long& d,
                                      unsigned long long a,
                                      unsigned long long b) {
    asm("fma.rn.f32x2 %0, %1, %2, %0;" : "+l"(d) : "l"(a), "l"(b));
}

// ---------------- 1) BatchNorm statistics: partial sums -----------------------
// grid 256, block 256. Block handles 128 rows; thread (c = t&63, rs = t>>6).
__global__ void k_bn_partial(const float* __restrict__ H) {
    int t = threadIdx.x;
    int c = t & 63, rs = t >> 6;
    int row0 = blockIdx.x * 128;
    float s = 0.f, q = 0.f;
    const float* p = H + (size_t)(row0 + rs) * 64 + c;
    #pragma unroll 8
    for (int r = 0; r < 128; r += 4) {
        float v = p[(size_t)r * 64];
        s += v;
        q += v * v;
    }
    __shared__ float ss[256], sq[256];
    ss[t] = s; sq[t] = q;
    __syncthreads();
    if (t < 64) {
        s = ss[t] + ss[t + 64] + ss[t + 128] + ss[t + 192];
        q = sq[t] + sq[t + 64] + sq[t + 128] + sq[t + 192];
        g_psum[blockIdx.x * 64 + t] = s;
        g_psq[blockIdx.x * 64 + t] = q;
    }
}

// ---------------- 2) finalize BN + fold scale/shift into W,b ------------------
// 1 block, 64 threads. Deterministic fixed-order sums.
__global__ void k_finalize(const float* __restrict__ gamma,
                           const float* __restrict__ beta,
                           const float* __restrict__ W,
                           const float* __restrict__ bias) {
    int c = threadIdx.x;  // 0..63
    float s = 0.f, q = 0.f;
    for (int i = 0; i < 256; i++) {
        s += g_psum[i * 64 + c];
        q += g_psq[i * 64 + c];
    }
    float mean = s * (1.0f / 32768.0f);
    float var  = q * (1.0f / 32768.0f) - mean * mean;  // biased variance
    float sc = gamma[c] * rsqrtf(var + BN_EPS);
    float sh = beta[c] - mean * sc;
    __shared__ float ssc[64], ssh[64];
    ssc[c] = sc; ssh[c] = sh;
    __syncthreads();
    int o = c;  // this thread now owns output column o of W'
    float bp = bias[o];
    for (int cc = 0; cc < 64; cc++) {
        float w = W[cc * 64 + o];
        g_Wp[cc * 64 + o] = ssc[cc] * w;
        bp += ssh[cc] * w;
    }
    g_bp[o] = bp;
}

// ---------------- 3) degree (row sums of A) ----------------------------------
// One warp per row, 8 warps/block, grid 4096. float4 coalesced reads.
__global__ void k_rowsum(const float* __restrict__ A) {
    int warp = threadIdx.x >> 5, lane = threadIdx.x & 31;
    int row = blockIdx.x * 8 + warp;
    const float4* p = (const float4*)A + (size_t)row * 256;
    float s = 0.f;
    #pragma unroll
    for (int it = 0; it < 8; it++) {
        float4 v = p[it * 32 + lane];
        s += (v.x + v.y) + (v.z + v.w);
    }
    #pragma unroll
    for (int off = 16; off; off >>= 1)
        s += __shfl_xor_sync(0xffffffffu, s, off);
    if (lane == 0) {
        g_sqd[row] = sqrtf(s);
        g_rsd[row] = rsqrtf(s);
    }
}

// ---------------- 4) Y = rsqrt(d) * (H @ W' + b') ----------------------------
// block 256, 16 rows/block, grid 2048.
__global__ void __launch_bounds__(256) k_computeY(const float* __restrict__ H) {
    __shared__ float Ws[64 * 64];
    __shared__ float hs[16 * 64];
    int t = threadIdx.x;
    for (int i = t; i < 4096; i += 256) Ws[i] = g_Wp[i];
    int row0 = blockIdx.x * 16;
    const float* Hp = H + (size_t)row0 * 64;
    for (int i = t; i < 1024; i += 256) hs[i] = Hp[i];
    __syncthreads();
    int o = t & 63, rq = t >> 6;
    for (int r = rq; r < 16; r += 4) {
        float acc = g_bp[o];
        const float* hr = hs + r * 64;
        #pragma unroll
        for (int cc = 0; cc < 64; cc++)
            acc += hr[cc] * Ws[cc * 64 + o];
        g_Y[(size_t)(row0 + r) * 64 + o] = acc * g_rsd[row0 + r];
    }
}

// ---------------- 5) main GEMM + epilogue ------------------------------------
// out[b,i,:] = leaky( sqrt(d_i) * ( Y[b,i,:] - sum_j A[b,i,j] * Y[b,j,:] ) )
// Tiles: BM=128, BN=64 (full), BK=32. Block 256 threads; thread tile 4x8
// (4 rows x 8 cols, cols packed as 4 f32x2 accumulators -> FFMA2).
__global__ void __launch_bounds__(256) k_gemm(const float* __restrict__ A,
                                              float* __restrict__ out) {
    __shared__ float  As[128 * 33];   // +1 pad: conflict-free stores & loads
    __shared__ float4 Bs[32 * 16];    // [32][64] floats

    int t = threadIdx.x;
    int batch = blockIdx.y;
    int i0 = blockIdx.x * 128;

    const float4* A4 = (const float4*)(A + (size_t)batch * NL * NL) + (size_t)i0 * 256;
    const float4* Y4 = (const float4*)(g_Y + (size_t)batch * NL * 64);

    int tx = t & 7;        // col group: cols tx*8 .. tx*8+7
    int ty = t >> 3;       // row group: rows ty*4 .. ty*4+3
    int lrow = t >> 3;     // load: row 0..31 (+32*it)
    int lk4  = t & 7;      // load: float4 index within 32-float K-slab

    unsigned long long acc[4][4];
    #pragma unroll
    for (int m = 0; m < 4; m++)
        #pragma unroll
        for (int n = 0; n < 4; n++) acc[m][n] = 0ull;

    for (int k0 = 0; k0 < 256; k0 += 8) {  // k0 in float4 units (K=1024)
        __syncthreads();
        // A tile: 128x32 floats. Coalesced float4 loads, scalar smem stores
        // (bank = (r + 4*lk4 + j) mod 32 -> conflict-free with pad 33).
        #pragma unroll
        for (int it = 0; it < 4; it++) {
            int r = lrow + it * 32;
            float4 v = A4[(size_t)r * 256 + k0 + lk4];
            float* d = As + r * 33 + lk4 * 4;
            d[0] = v.x; d[1] = v.y; d[2] = v.z; d[3] = v.w;
        }
        // Y tile: 32x64 floats = 512 float4.
        #pragma unroll
        for (int it = 0; it < 2; it++) {
            int idx = t + it * 256;
            int r = idx >> 4, c4 = idx & 15;
            Bs[idx] = Y4[(size_t)(k0 * 4 + r) * 16 + c4];
        }
        __syncthreads();

        #pragma unroll
        for (int k = 0; k < 32; k++) {
            const ulonglong2* bp = (const ulonglong2*)(Bs + k * 16 + tx * 2);
            ulonglong2 b01 = bp[0], b23 = bp[1];
            unsigned long long b[4] = {b01.x, b01.y, b23.x, b23.y};
            #pragma unroll
            for (int m = 0; m < 4; m++) {
                float a = As[(ty * 4 + m) * 33 + k];
                unsigned long long ap = pack2(a);
                ffma2(acc[m][0], ap, b[0]);
                ffma2(acc[m][1], ap, b[1]);
                ffma2(acc[m][2], ap, b[2]);
                ffma2(acc[m][3], ap, b[3]);
            }
        }
    }

    // Epilogue
    float* outb = out + (size_t)batch * NL * 64;
    const float* Yb = g_Y + (size_t)batch * NL * 64;
    #pragma unroll
    for (int m = 0; m < 4; m++) {
        int row = ty * 4 + m;
        float s = g_sqd[batch * NL + i0 + row];
        #pragma unroll
        for (int n = 0; n < 4; n++) {
            float2 av = *(float2*)&acc[m][n];
            int col = tx * 8 + n * 2;
            float2 y = *(const float2*)(Yb + (size_t)(i0 + row) * 64 + col);
            float v0 = s * (y.x - av.x);
            float v1 = s * (y.y - av.y);
            v0 = v0 > 0.f ? v0 : 0.01f * v0;
            v1 = v1 > 0.f ? v1 : 0.01f * v1;
            *(float2*)(outb + (size_t)(i0 + row) * 64 + col) = make_float2(v0, v1);
        }
    }
}

// ---------------- launch -----------------------------------------------------
extern "C" void kernel_launch(void* const* d_in, const int* in_sizes, int n_in,
                              void* d_out, int out_size) {
    (void)in_sizes; (void)n_in; (void)out_size;
    const float* H     = (const float*)d_in[0];
    const float* A     = (const float*)d_in[1];
    const float* gamma = (const float*)d_in[2];
    const float* beta  = (const float*)d_in[3];
    const float* W     = (const float*)d_in[4];
    const float* bias  = (const float*)d_in[5];
    float* out = (float*)d_out;

    k_bn_partial<<<256, 256>>>(H);
    k_finalize<<<1, 64>>>(gamma, beta, W, bias);
    k_rowsum<<<4096, 256>>>(A);
    k_computeY<<<2048, 256>>>(H);
    k_gemm<<<dim3(8, NB), 256>>>(A, out);
}

// round 3
// speedup vs baseline: 1.5624x; 1.5624x over previous
#include <cuda_runtime.h>
#include <cuda_bf16.h>
#include <cstdint>

// Problem sizes (fixed by the reference)
#define NB 32
#define NL 1024
#define NC 64
#define NROWS (NB * NL)          // 32768
#define BN_EPS 1e-5f

// ---------------- scratch (device globals; no allocations allowed) ----------
__device__ float g_psum[256 * 64];
__device__ float g_psq[256 * 64];
__device__ float g_Wp[64 * 64];                 // scale-folded weight
__device__ float g_bp[64];                      // shift-folded bias
__device__ float g_sqd[NROWS];                  // sqrt(degree)
__device__ float g_rsd[NROWS];                  // rsqrt(degree)
__device__ float g_X[NROWS * 64];               // X = Hn @ W' + b' (fp32), 8 MB
__device__ __nv_bfloat16 g_Xt_hi[NB * 64 * NL]; // X^T per batch [b][n][l], hi part
__device__ __nv_bfloat16 g_Xt_lo[NB * 64 * NL]; // lo part

// ---------------- helpers ----------------------------------------------------
__device__ __forceinline__ unsigned long long pack2(float a) {
    unsigned long long r;
    asm("mov.b64 %0, {%1, %1};" : "=l"(r) : "f"(a));
    return r;
}
__device__ __forceinline__ void ffma2(unsigned long long& d,
                                      unsigned long long a,
                                      unsigned long long b) {
    asm("fma.rn.f32x2 %0, %1, %2, %0;" : "+l"(d) : "l"(a), "l"(b));
}
__device__ __forceinline__ void ldsm4(uint32_t* r, const __nv_bfloat16* p) {
    uint32_t a = (uint32_t)__cvta_generic_to_shared((const void*)p);
    asm volatile("ldmatrix.sync.aligned.m8n8.x4.shared.b16 {%0,%1,%2,%3}, [%4];"
                 : "=r"(r[0]), "=r"(r[1]), "=r"(r[2]), "=r"(r[3]) : "r"(a));
}
__device__ __forceinline__ void mma16816(float* c, const uint32_t* a,
                                         uint32_t b0, uint32_t b1) {
    asm volatile(
        "mma.sync.aligned.m16n8k16.row.col.f32.bf16.bf16.f32 "
        "{%0,%1,%2,%3}, {%4,%5,%6,%7}, {%8,%9}, {%0,%1,%2,%3};"
        : "+f"(c[0]), "+f"(c[1]), "+f"(c[2]), "+f"(c[3])
        : "r"(a[0]), "r"(a[1]), "r"(a[2]), "r"(a[3]), "r"(b0), "r"(b1));
}
// split x into bf16 hi/lo pairs, packed as bf16x2 words
__device__ __forceinline__ void split2(float x0, float x1,
                                       uint32_t& hi, uint32_t& lo) {
    __nv_bfloat162 h = __float22bfloat162_rn(make_float2(x0, x1));
    float2 hf = __bfloat1622float2(h);
    __nv_bfloat162 l = __float22bfloat162_rn(make_float2(x0 - hf.x, x1 - hf.y));
    hi = *(uint32_t*)&h;
    lo = *(uint32_t*)&l;
}

// ---------------- 1) BatchNorm statistics: partial sums ----------------------
__global__ void k_bn_partial(const float* __restrict__ H) {
    int t = threadIdx.x;
    int c = t & 63, rs = t >> 6;
    int row0 = blockIdx.x * 128;
    float s = 0.f, q = 0.f;
    const float* p = H + (size_t)(row0 + rs) * 64 + c;
    #pragma unroll 8
    for (int r = 0; r < 128; r += 4) {
        float v = p[(size_t)r * 64];
        s += v;
        q += v * v;
    }
    __shared__ float ss[256], sq[256];
    ss[t] = s; sq[t] = q;
    __syncthreads();
    if (t < 64) {
        s = ss[t] + ss[t + 64] + ss[t + 128] + ss[t + 192];
        q = sq[t] + sq[t + 64] + sq[t + 128] + sq[t + 192];
        g_psum[blockIdx.x * 64 + t] = s;
        g_psq[blockIdx.x * 64 + t] = q;
    }
}

// ---------------- 2) finalize BN + fold scale/shift into W,b -----------------
__global__ void k_finalize(const float* __restrict__ gamma,
                           const float* __restrict__ beta,
                           const float* __restrict__ W,
                           const float* __restrict__ bias) {
    int c = threadIdx.x;  // 0..63
    float s = 0.f, q = 0.f;
    for (int i = 0; i < 256; i++) {
        s += g_psum[i * 64 + c];
        q += g_psq[i * 64 + c];
    }
    float mean = s * (1.0f / 32768.0f);
    float var  = q * (1.0f / 32768.0f) - mean * mean;  // biased variance
    float sc = gamma[c] * rsqrtf(var + BN_EPS);
    float sh = beta[c] - mean * sc;
    __shared__ float ssc[64], ssh[64];
    ssc[c] = sc; ssh[c] = sh;
    __syncthreads();
    int o = c;
    float bp = bias[o];
    for (int cc = 0; cc < 64; cc++) {
        float w = W[cc * 64 + o];
        g_Wp[cc * 64 + o] = ssc[cc] * w;
        bp += ssh[cc] * w;
    }
    g_bp[o] = bp;
}

// ---------------- 3) degree (row sums of A) ----------------------------------
__global__ void k_rowsum(const float* __restrict__ A) {
    int warp = threadIdx.x >> 5, lane = threadIdx.x & 31;
    int row = blockIdx.x * 8 + warp;
    const float4* p = (const float4*)A + (size_t)row * 256;
    float s = 0.f;
    #pragma unroll
    for (int it = 0; it < 8; it++) {
        float4 v = p[it * 32 + lane];
        s += (v.x + v.y) + (v.z + v.w);
    }
    #pragma unroll
    for (int off = 16; off; off >>= 1)
        s += __shfl_xor_sync(0xffffffffu, s, off);
    if (lane == 0) {
        g_sqd[row] = sqrtf(s);
        g_rsd[row] = rsqrtf(s);
    }
}

// ---------------- 4) X = Hn@W'+b' (fp32 + transposed bf16 hi/lo) -------------
// block 256, 32 rows/block, grid 1024. Thread: 1 row x 8 cols, FFMA2.
__global__ void __launch_bounds__(256) k_computeX(const float* __restrict__ H) {
    __shared__ float Ws[64 * 64];    // 16 KB
    __shared__ float hs[32 * 64];    // 8 KB
    __shared__ float ys[64 * 33];    // transposed staging (pad 33)
    int t = threadIdx.x;
    for (int i = t; i < 4096; i += 256) Ws[i] = g_Wp[i];
    int row0 = blockIdx.x * 32;
    const float4* Hp = (const float4*)(H + (size_t)row0 * 64);
    #pragma unroll
    for (int it = 0; it < 2; it++)
        ((float4*)hs)[t + it * 256] = Hp[t + it * 256];
    __syncthreads();

    int tx = t & 7, row = t >> 3;  // cols tx*8..tx*8+7, row 0..31
    unsigned long long acc[4];
    {
        const ulonglong2* bp2 = (const ulonglong2*)(g_bp + tx * 8);
        ulonglong2 b0 = bp2[0], b1 = bp2[1];
        acc[0] = b0.x; acc[1] = b0.y; acc[2] = b1.x; acc[3] = b1.y;
    }
    const float* hr = hs + row * 64;
    #pragma unroll
    for (int cc = 0; cc < 64; cc++) {
        unsigned long long h2 = pack2(hr[cc]);
        const ulonglong2* wp = (const ulonglong2*)(Ws + cc * 64 + tx * 8);
        ulonglong2 w0 = wp[0], w1 = wp[1];
        ffma2(acc[0], h2, w0.x);
        ffma2(acc[1], h2, w0.y);
        ffma2(acc[2], h2, w1.x);
        ffma2(acc[3], h2, w1.y);
    }
    // write fp32 X (coalesced)
    float2 a0 = *(float2*)&acc[0], a1 = *(float2*)&acc[1];
    float2 a2 = *(float2*)&acc[2], a3 = *(float2*)&acc[3];
    {
        float* gx = g_X + (size_t)(row0 + row) * 64 + tx * 8;
        *(float4*)gx       = make_float4(a0.x, a0.y, a1.x, a1.y);
        *(float4*)(gx + 4) = make_float4(a2.x, a2.y, a3.x, a3.y);
    }
    // stage transposed in smem
    float v[8] = {a0.x, a0.y, a1.x, a1.y, a2.x, a2.y, a3.x, a3.y};
    #pragma unroll
    for (int c = 0; c < 8; c++) ys[(tx * 8 + c) * 33 + row] = v[c];
    __syncthreads();

    // transposed bf16 hi/lo writes: thread -> (n = t>>2, part = t&3), 8 l's
    int n = t >> 2, part = t & 3;
    int b = row0 >> 10, l0 = (row0 & 1023) + part * 8;
    uint32_t uh[4], ul[4];
    #pragma unroll
    for (int e = 0; e < 4; e++) {
        float x0 = ys[n * 33 + part * 8 + 2 * e];
        float x1 = ys[n * 33 + part * 8 + 2 * e + 1];
        split2(x0, x1, uh[e], ul[e]);
    }
    size_t dst = ((size_t)(b * 64 + n) << 10) + l0;
    *(uint4*)(g_Xt_hi + dst) = make_uint4(uh[0], uh[1], uh[2], uh[3]);
    *(uint4*)(g_Xt_lo + dst) = make_uint4(ul[0], ul[1], ul[2], ul[3]);
}

// ---------------- 5) HMMA GEMM + epilogue ------------------------------------
// D[i,n] = sum_j (A[i,j]*rsd[j]) * X[j,n]   (bf16 hi/lo split, fp32 accum)
// out[i,n] = leaky( X[i,n] - sqd[i] * D[i,n] )
// Block: 128x64 tile, BK=32, 8 warps each 32x32 (2x4 m16n8k16 tiles).
#define APAD 40   // bf16 row stride: 80B -> ldmatrix row bases hit distinct banks

__global__ void __launch_bounds__(256) k_gemm_mma(const float* __restrict__ A,
                                                  float* __restrict__ out) {
    __shared__ __align__(16) __nv_bfloat16 As_hi[128 * APAD];
    __shared__ __align__(16) __nv_bfloat16 As_lo[128 * APAD];
    __shared__ __align__(16) __nv_bfloat16 Bs_hi[64 * APAD];
    __shared__ __align__(16) __nv_bfloat16 Bs_lo[64 * APAD];

    int t = threadIdx.x, wid = t >> 5, lane = t & 31;
    int b = blockIdx.y, i0 = blockIdx.x * 128;
    int wm = wid & 3, wn = wid >> 2;   // warp tile: rows wm*32.., cols wn*32..

    float c[2][4][4];
    #pragma unroll
    for (int mi = 0; mi < 2; mi++)
        #pragma unroll
        for (int ni = 0; ni < 4; ni++)
            #pragma unroll
            for (int r = 0; r < 4; r++) c[mi][ni][r] = 0.f;

    const float4* A4 = (const float4*)(A + (size_t)b * NL * NL) + (size_t)i0 * 256;
    const float* rsd_b = g_rsd + (size_t)b * NL;

    int lm = t >> 3, lk4 = t & 7;   // A loader: rows lm+32*it, float4 col lk4
    int ln = t >> 2, lk8 = t & 3;   // B loader: row ln, uint4 col lk8

    // ldmatrix source rows (per-thread, loop-invariant)
    int qr = (lane & 7) + ((lane & 8) ? 8 : 0);
    int qk = (lane & 16) ? 8 : 0;

    for (int ch = 0; ch < 32; ch++) {
        int jc = ch * 32;
        // ---- A tile: 128x32 fp32 -> scaled bf16 hi/lo ----
        float4 rs4 = __ldg((const float4*)(rsd_b + jc) + lk4);
        #pragma unroll
        for (int it = 0; it < 4; it++) {
            int m = lm + it * 32;
            float4 v = __ldg(&A4[(size_t)m * 256 + (jc >> 2) + lk4]);
            v.x *= rs4.x; v.y *= rs4.y; v.z *= rs4.z; v.w *= rs4.w;
            uint2 uh, ul;
            split2(v.x, v.y, uh.x, ul.x);
            split2(v.z, v.w, uh.y, ul.y);
            *(uint2*)&As_hi[m * APAD + lk4 * 4] = uh;
            *(uint2*)&As_lo[m * APAD + lk4 * 4] = ul;
        }
        // ---- B tile: Xt[b][n][jc..jc+31] bf16 hi/lo straight copy ----
        {
            size_t e = ((size_t)(b * 64 + ln) << 10) + jc + lk8 * 8;
            *(uint4*)&Bs_hi[ln * APAD + lk8 * 8] = __ldg((const uint4*)(g_Xt_hi + e));
            *(uint4*)&Bs_lo[ln * APAD + lk8 * 8] = __ldg((const uint4*)(g_Xt_lo + e));
        }
        __syncthreads();

        #pragma unroll
        for (int kk = 0; kk < 2; kk++) {
            int k0 = kk * 16 + qk;
            uint32_t ah[2][4], al[2][4], bh[2][4], bl[2][4];
            #pragma unroll
            for (int mi = 0; mi < 2; mi++) {
                int r = (wm * 32 + mi * 16 + qr) * APAD + k0;
                ldsm4(ah[mi], As_hi + r);
                ldsm4(al[mi], As_lo + r);
            }
            #pragma unroll
            for (int nj = 0; nj < 2; nj++) {
                int r = (wn * 32 + nj * 16 + qr) * APAD + k0;
                ldsm4(bh[nj], Bs_hi + r);
                ldsm4(bl[nj], Bs_lo + r);
            }
            #pragma unroll
            for (int mi = 0; mi < 2; mi++)
                #pragma unroll
                for (int ni = 0; ni < 4; ni++) {
                    int g = ni >> 1, s = ni & 1;
                    mma16816(c[mi][ni], ah[mi], bh[g][s], bh[g][s + 2]);
                    mma16816(c[mi][ni], ah[mi], bl[g][s], bl[g][s + 2]);
                    mma16816(c[mi][ni], al[mi], bh[g][s], bh[g][s + 2]);
                }
        }
        __syncthreads();
    }

    // ---- epilogue: out = leaky(X - sqd * D), straight from fragments ----
    float* outb = out + (size_t)b * NL * 64;
    const float* Xb = g_X + (size_t)b * NL * 64;
    const float* sqd_b = g_sqd + (size_t)b * NL;
    int r0 = i0 + wm * 32 + (lane >> 2);
    int cbase = wn * 32 + (lane & 3) * 2;
    #pragma unroll
    for (int mi = 0; mi < 2; mi++) {
        #pragma unroll
        for (int half = 0; half < 2; half++) {
            int row = r0 + mi * 16 + half * 8;
            float sq = __ldg(sqd_b + row);
            #pragma unroll
            for (int ni = 0; ni < 4; ni++) {
                int col = cbase + ni * 8;
                float2 x = *(const float2*)(Xb + (size_t)row * 64 + col);
                float v0 = x.x - sq * c[mi][ni][half * 2 + 0];
                float v1 = x.y - sq * c[mi][ni][half * 2 + 1];
                v0 = v0 > 0.f ? v0 : 0.01f * v0;
                v1 = v1 > 0.f ? v1 : 0.01f * v1;
                *(float2*)(outb + (size_t)row * 64 + col) = make_float2(v0, v1);
            }
        }
    }
}

// ---------------- launch -----------------------------------------------------
extern "C" void kernel_launch(void* const* d_in, const int* in_sizes, int n_in,
                              void* d_out, int out_size) {
    (void)in_sizes; (void)n_in; (void)out_size;
    const float* H     = (const float*)d_in[0];
    const float* A     = (const float*)d_in[1];
    const float* gamma = (const float*)d_in[2];
    const float* beta  = (const float*)d_in[3];
    const float* W     = (const float*)d_in[4];
    const float* bias  = (const float*)d_in[5];
    float* out = (float*)d_out;

    k_bn_partial<<<256, 256>>>(H);
    k_finalize<<<1, 64>>>(gamma, beta, W, bias);
    k_computeX<<<1024, 256>>>(H);
    k_rowsum<<<4096, 256>>>(A);
    k_gemm_mma<<<dim3(8, NB), 256>>>(A, out);
}

// round 4
// speedup vs baseline: 1.6304x; 1.0435x over previous
#include <cuda_runtime.h>
#include <cuda_bf16.h>
#include <cstdint>

// Problem sizes (fixed by the reference)
#define NB 32
#define NL 1024
#define NC 64
#define NROWS (NB * NL)          // 32768
#define BN_EPS 1e-5f

// ---------------- scratch (device globals; no allocations allowed) ----------
__device__ float g_psum[256 * 64];
__device__ float g_psq[256 * 64];
__device__ float g_Wp[64 * 64];                 // scale-folded weight
__device__ float g_bp[64];                      // shift-folded bias
__device__ float g_sqd[NROWS];                  // sqrt(degree)
__device__ float g_rsd[NROWS];                  // rsqrt(degree)
__device__ float g_X[NROWS * 64];               // X = Hn @ W' + b' (fp32), 8 MB
__device__ __nv_bfloat16 g_Yt_hi[NB * 64 * NL]; // (rsd*X)^T per batch [b][n][l]
__device__ __nv_bfloat16 g_Yt_lo[NB * 64 * NL]; // lo part

// ---------------- helpers ----------------------------------------------------
__device__ __forceinline__ unsigned long long pack2(float a) {
    unsigned long long r;
    asm("mov.b64 %0, {%1, %1};" : "=l"(r) : "f"(a));
    return r;
}
__device__ __forceinline__ void ffma2(unsigned long long& d,
                                      unsigned long long a,
                                      unsigned long long b) {
    asm("fma.rn.f32x2 %0, %1, %2, %0;" : "+l"(d) : "l"(a), "l"(b));
}
__device__ __forceinline__ void ldsm4(uint32_t* r, const __nv_bfloat16* p) {
    uint32_t a = (uint32_t)__cvta_generic_to_shared((const void*)p);
    asm volatile("ldmatrix.sync.aligned.m8n8.x4.shared.b16 {%0,%1,%2,%3}, [%4];"
                 : "=r"(r[0]), "=r"(r[1]), "=r"(r[2]), "=r"(r[3]) : "r"(a));
}
__device__ __forceinline__ void mma16816(float* c, const uint32_t* a,
                                         uint32_t b0, uint32_t b1) {
    asm volatile(
        "mma.sync.aligned.m16n8k16.row.col.f32.bf16.bf16.f32 "
        "{%0,%1,%2,%3}, {%4,%5,%6,%7}, {%8,%9}, {%0,%1,%2,%3};"
        : "+f"(c[0]), "+f"(c[1]), "+f"(c[2]), "+f"(c[3])
        : "r"(a[0]), "r"(a[1]), "r"(a[2]), "r"(a[3]), "r"(b0), "r"(b1));
}
// split x into bf16 hi/lo pairs, packed as bf16x2 words
__device__ __forceinline__ void split2(float x0, float x1,
                                       uint32_t& hi, uint32_t& lo) {
    __nv_bfloat162 h = __float22bfloat162_rn(make_float2(x0, x1));
    float2 hf = __bfloat1622float2(h);
    __nv_bfloat162 l = __float22bfloat162_rn(make_float2(x0 - hf.x, x1 - hf.y));
    hi = *(uint32_t*)&h;
    lo = *(uint32_t*)&l;
}

// ---------------- 1) BatchNorm statistics: partial sums ----------------------
__global__ void k_bn_partial(const float* __restrict__ H) {
    int t = threadIdx.x;
    int c = t & 63, rs = t >> 6;
    int row0 = blockIdx.x * 128;
    float s = 0.f, q = 0.f;
    const float* p = H + (size_t)(row0 + rs) * 64 + c;
    #pragma unroll 8
    for (int r = 0; r < 128; r += 4) {
        float v = p[(size_t)r * 64];
        s += v;
        q += v * v;
    }
    __shared__ float ss[256], sq[256];
    ss[t] = s; sq[t] = q;
    __syncthreads();
    if (t < 64) {
        s = ss[t] + ss[t + 64] + ss[t + 128] + ss[t + 192];
        q = sq[t] + sq[t + 64] + sq[t + 128] + sq[t + 192];
        g_psum[blockIdx.x * 64 + t] = s;
        g_psq[blockIdx.x * 64 + t] = q;
    }
}

// ---------------- 2) finalize BN + fold scale/shift into W,b -----------------
__global__ void k_finalize(const float* __restrict__ gamma,
                           const float* __restrict__ beta,
                           const float* __restrict__ W,
                           const float* __restrict__ bias) {
    int c = threadIdx.x;  // 0..63
    float s = 0.f, q = 0.f;
    for (int i = 0; i < 256; i++) {
        s += g_psum[i * 64 + c];
        q += g_psq[i * 64 + c];
    }
    float mean = s * (1.0f / 32768.0f);
    float var  = q * (1.0f / 32768.0f) - mean * mean;  // biased variance
    float sc = gamma[c] * rsqrtf(var + BN_EPS);
    float sh = beta[c] - mean * sc;
    __shared__ float ssc[64], ssh[64];
    ssc[c] = sc; ssh[c] = sh;
    __syncthreads();
    int o = c;
    float bp = bias[o];
    for (int cc = 0; cc < 64; cc++) {
        float w = W[cc * 64 + o];
        g_Wp[cc * 64 + o] = ssc[cc] * w;
        bp += ssh[cc] * w;
    }
    g_bp[o] = bp;
}

// ---------------- 3) degree (row sums of A) ----------------------------------
__global__ void k_rowsum(const float* __restrict__ A) {
    int warp = threadIdx.x >> 5, lane = threadIdx.x & 31;
    int row = blockIdx.x * 8 + warp;
    const float4* p = (const float4*)A + (size_t)row * 256;
    float s = 0.f;
    #pragma unroll
    for (int it = 0; it < 8; it++) {
        float4 v = p[it * 32 + lane];
        s += (v.x + v.y) + (v.z + v.w);
    }
    #pragma unroll
    for (int off = 16; off; off >>= 1)
        s += __shfl_xor_sync(0xffffffffu, s, off);
    if (lane == 0) {
        g_sqd[row] = sqrtf(s);
        g_rsd[row] = rsqrtf(s);
    }
}

// ---------------- 4) X = Hn@W'+b'; Yt = (rsd*X)^T bf16 hi/lo -----------------
// block 256, 32 rows/block, grid 1024. Thread: 1 row x 8 cols, FFMA2.
__global__ void __launch_bounds__(256) k_computeX(const float* __restrict__ H) {
    __shared__ float Ws[64 * 64];    // 16 KB
    __shared__ float hs[32 * 64];    // 8 KB
    __shared__ float ys[64 * 33];    // transposed staging (pad 33)
    __shared__ float rs[32];
    int t = threadIdx.x;
    int row0 = blockIdx.x * 32;
    for (int i = t; i < 4096; i += 256) Ws[i] = g_Wp[i];
    if (t < 32) rs[t] = g_rsd[row0 + t];
    const float4* Hp = (const float4*)(H + (size_t)row0 * 64);
    #pragma unroll
    for (int it = 0; it < 2; it++)
        ((float4*)hs)[t + it * 256] = Hp[t + it * 256];
    __syncthreads();

    int tx = t & 7, row = t >> 3;  // cols tx*8..tx*8+7, row 0..31
    unsigned long long acc[4];
    {
        const ulonglong2* bp2 = (const ulonglong2*)(g_bp + tx * 8);
        ulonglong2 b0 = bp2[0], b1 = bp2[1];
        acc[0] = b0.x; acc[1] = b0.y; acc[2] = b1.x; acc[3] = b1.y;
    }
    const float* hr = hs + row * 64;
    #pragma unroll
    for (int cc = 0; cc < 64; cc++) {
        unsigned long long h2 = pack2(hr[cc]);
        const ulonglong2* wp = (const ulonglong2*)(Ws + cc * 64 + tx * 8);
        ulonglong2 w0 = wp[0], w1 = wp[1];
        ffma2(acc[0], h2, w0.x);
        ffma2(acc[1], h2, w0.y);
        ffma2(acc[2], h2, w1.x);
        ffma2(acc[3], h2, w1.y);
    }
    // write fp32 X (coalesced)
    float2 a0 = *(float2*)&acc[0], a1 = *(float2*)&acc[1];
    float2 a2 = *(float2*)&acc[2], a3 = *(float2*)&acc[3];
    {
        float* gx = g_X + (size_t)(row0 + row) * 64 + tx * 8;
        *(float4*)gx       = make_float4(a0.x, a0.y, a1.x, a1.y);
        *(float4*)(gx + 4) = make_float4(a2.x, a2.y, a3.x, a3.y);
    }
    // stage transposed in smem
    float v[8] = {a0.x, a0.y, a1.x, a1.y, a2.x, a2.y, a3.x, a3.y};
    #pragma unroll
    for (int c = 0; c < 8; c++) ys[(tx * 8 + c) * 33 + row] = v[c];
    __syncthreads();

    // transposed, rsd-scaled bf16 hi/lo writes: thread -> (n = t>>2, part = t&3)
    int n = t >> 2, part = t & 3;
    int b = row0 >> 10, l0 = (row0 & 1023) + part * 8;
    uint32_t uh[4], ul[4];
    #pragma unroll
    for (int e = 0; e < 4; e++) {
        int li = part * 8 + 2 * e;
        float x0 = ys[n * 33 + li]     * rs[li];
        float x1 = ys[n * 33 + li + 1] * rs[li + 1];
        split2(x0, x1, uh[e], ul[e]);
    }
    size_t dst = ((size_t)(b * 64 + n) << 10) + l0;
    *(uint4*)(g_Yt_hi + dst) = make_uint4(uh[0], uh[1], uh[2], uh[3]);
    *(uint4*)(g_Yt_lo + dst) = make_uint4(ul[0], ul[1], ul[2], ul[3]);
}

// ---------------- 5) pipelined HMMA GEMM + epilogue --------------------------
// D[i,n] = sum_j A[i,j] * Y[j,n]   (bf16 hi/lo split, fp32 accum)
// out[i,n] = leaky( X[i,n] - sqd[i] * D[i,n] )
// Block: 128x64 tile, BK=32, 8 warps each 32x32 (2x4 m16n8k16 tiles).
// Double-buffered smem + register prefetch; one __syncthreads per chunk.
#define APAD 40          // bf16 row stride (80B)
#define ST_ELEMS 15360   // per-stage smem elements: A hi/lo 2*5120 + B hi/lo 2*2560
#define DYN_SMEM (2 * ST_ELEMS * 2)
#define NCHUNK 32

__global__ void __launch_bounds__(256, 2) k_gemm_mma(const float* __restrict__ A,
                                                     float* __restrict__ out) {
    extern __shared__ __align__(16) __nv_bfloat16 sm[];

    int t = threadIdx.x, wid = t >> 5, lane = t & 31;
    int b = blockIdx.y, i0 = blockIdx.x * 128;
    int wm = wid & 3, wn = wid >> 2;   // warp tile: rows wm*32.., cols wn*32..

    float c[2][4][4];
    #pragma unroll
    for (int mi = 0; mi < 2; mi++)
        #pragma unroll
        for (int ni = 0; ni < 4; ni++)
            #pragma unroll
            for (int r = 0; r < 4; r++) c[mi][ni][r] = 0.f;

    const float4* A4 = (const float4*)(A + (size_t)b * NL * NL) + (size_t)i0 * 256;
    int lm = t >> 3, lk4 = t & 7;   // A loader: rows lm+32*it, float4 col lk4
    int ln = t >> 2, lk8 = t & 3;   // B loader: row ln, uint4 col lk8

    // ldmatrix source rows (per-thread, loop-invariant)
    int qr = (lane & 7) + ((lane & 8) ? 8 : 0);
    int qk = (lane & 16) ? 8 : 0;

    float4 ra[4];      // prefetched A chunk (fp32)
    uint4 rbh, rbl;    // prefetched B chunk (bf16 hi/lo)

    auto LDG = [&](int ch) {
        int jc = ch * 32;
        #pragma unroll
        for (int it = 0; it < 4; it++)
            ra[it] = __ldg(&A4[(size_t)(lm + 32 * it) * 256 + (jc >> 2) + lk4]);
        size_t e = ((size_t)(b * 64 + ln) << 10) + jc + lk8 * 8;
        rbh = __ldg((const uint4*)(g_Yt_hi + e));
        rbl = __ldg((const uint4*)(g_Yt_lo + e));
    };
    auto STS = [&](int s) {
        __nv_bfloat16* Ah = sm + s * ST_ELEMS;
        __nv_bfloat16* Al = Ah + 5120;
        __nv_bfloat16* Bh = Ah + 10240;
        __nv_bfloat16* Bl = Ah + 12800;
        #pragma unroll
        for (int it = 0; it < 4; it++) {
            uint2 uh, ul;
            split2(ra[it].x, ra[it].y, uh.x, ul.x);
            split2(ra[it].z, ra[it].w, uh.y, ul.y);
            *(uint2*)&Ah[(lm + 32 * it) * APAD + lk4 * 4] = uh;
            *(uint2*)&Al[(lm + 32 * it) * APAD + lk4 * 4] = ul;
        }
        *(uint4*)&Bh[ln * APAD + lk8 * 8] = rbh;
        *(uint4*)&Bl[ln * APAD + lk8 * 8] = rbl;
    };

    LDG(0);
    STS(0);
    LDG(1);
    __syncthreads();

    #pragma unroll 1
    for (int ch = 0; ch < NCHUNK; ch++) {
        int cur = ch & 1;
        if (ch + 1 < NCHUNK) STS(cur ^ 1);   // store prefetched chunk ch+1
        if (ch + 2 < NCHUNK) LDG(ch + 2);    // issue loads early (hide DRAM)

        const __nv_bfloat16* Ah = sm + cur * ST_ELEMS;
        const __nv_bfloat16* Al = Ah + 5120;
        const __nv_bfloat16* Bh = Ah + 10240;
        const __nv_bfloat16* Bl = Ah + 12800;
        #pragma unroll
        for (int kk = 0; kk < 2; kk++) {
            int k0 = kk * 16 + qk;
            uint32_t ah[2][4], al[2][4], bh[2][4], bl[2][4];
            #pragma unroll
            for (int mi = 0; mi < 2; mi++) {
                int r = (wm * 32 + mi * 16 + qr) * APAD + k0;
                ldsm4(ah[mi], Ah + r);
                ldsm4(al[mi], Al + r);
            }
            #pragma unroll
            for (int nj = 0; nj < 2; nj++) {
                int r = (wn * 32 + nj * 16 + qr) * APAD + k0;
                ldsm4(bh[nj], Bh + r);
                ldsm4(bl[nj], Bl + r);
            }
            #pragma unroll
            for (int mi = 0; mi < 2; mi++)
                #pragma unroll
                for (int ni = 0; ni < 4; ni++) {
                    int g = ni >> 1, s = ni & 1;
                    mma16816(c[mi][ni], ah[mi], bh[g][s], bh[g][s + 2]);
                    mma16816(c[mi][ni], ah[mi], bl[g][s], bl[g][s + 2]);
                    mma16816(c[mi][ni], al[mi], bh[g][s], bh[g][s + 2]);
                }
        }
        __syncthreads();
    }

    // ---- epilogue: out = leaky(X - sqd * D), straight from fragments ----
    float* outb = out + (size_t)b * NL * 64;
    const float* Xb = g_X + (size_t)b * NL * 64;
    const float* sqd_b = g_sqd + (size_t)b * NL;
    int r0 = i0 + wm * 32 + (lane >> 2);
    int cbase = wn * 32 + (lane & 3) * 2;
    #pragma unroll
    for (int mi = 0; mi < 2; mi++) {
        #pragma unroll
        for (int half = 0; half < 2; half++) {
            int row = r0 + mi * 16 + half * 8;
            float sq = __ldg(sqd_b + row);
            #pragma unroll
            for (int ni = 0; ni < 4; ni++) {
                int col = cbase + ni * 8;
                float2 x = *(const float2*)(Xb + (size_t)row * 64 + col);
                float v0 = x.x - sq * c[mi][ni][half * 2 + 0];
                float v1 = x.y - sq * c[mi][ni][half * 2 + 1];
                v0 = v0 > 0.f ? v0 : 0.01f * v0;
                v1 = v1 > 0.f ? v1 : 0.01f * v1;
                *(float2*)(outb + (size_t)row * 64 + col) = make_float2(v0, v1);
            }
        }
    }
}

// ---------------- launch -----------------------------------------------------
extern "C" void kernel_launch(void* const* d_in, const int* in_sizes, int n_in,
                              void* d_out, int out_size) {
    (void)in_sizes; (void)n_in; (void)out_size;
    const float* H     = (const float*)d_in[0];
    const float* A     = (const float*)d_in[1];
    const float* gamma = (const float*)d_in[2];
    const float* beta  = (const float*)d_in[3];
    const float* W     = (const float*)d_in[4];
    const float* bias  = (const float*)d_in[5];
    float* out = (float*)d_out;

    cudaFuncSetAttribute(k_gemm_mma, cudaFuncAttributeMaxDynamicSharedMemorySize,
                         DYN_SMEM);

    k_bn_partial<<<256, 256>>>(H);
    k_rowsum<<<4096, 256>>>(A);
    k_finalize<<<1, 64>>>(gamma, beta, W, bias);
    k_computeX<<<1024, 256>>>(H);
    k_gemm_mma<<<dim3(8, NB), 256, DYN_SMEM>>>(A, out);
}

// round 10
// speedup vs baseline: 1.9680x; 1.2070x over previous
#include <cuda_runtime.h>
#include <cuda_bf16.h>
#include <cstdint>

// Problem sizes (fixed by the reference)
#define NB 32
#define NL 1024
#define NC 64
#define NROWS (NB * NL)          // 32768
#define BN_EPS 1e-5f

// ---------------- scratch (device globals; no allocations allowed) ----------
__device__ float g_psum[256 * 64];
__device__ float g_psq[256 * 64];
__device__ float g_bp[64];                      // shift-folded bias
__device__ __nv_bfloat16 g_Wt_hi[64 * 64];      // (scale-folded W)^T hi [o][c]
__device__ __nv_bfloat16 g_Wt_lo[64 * 64];      // lo part
__device__ float g_sqd[NROWS];                  // sqrt(degree)
__device__ float g_rsd[NROWS];                  // rsqrt(degree)
__device__ float g_X[NROWS * 64];               // X = Hn @ W' + b' (fp32), 8 MB
__device__ __nv_bfloat16 g_Yt_hi[NB * 64 * NL]; // (rsd*X)^T per batch [b][n][l]
__device__ __nv_bfloat16 g_Yt_lo[NB * 64 * NL]; // lo part

// ---------------- helpers ----------------------------------------------------
__device__ __forceinline__ void ldsm4(uint32_t* r, const __nv_bfloat16* p) {
    uint32_t a = (uint32_t)__cvta_generic_to_shared((const void*)p);
    asm volatile("ldmatrix.sync.aligned.m8n8.x4.shared.b16 {%0,%1,%2,%3}, [%4];"
                 : "=r"(r[0]), "=r"(r[1]), "=r"(r[2]), "=r"(r[3]) : "r"(a));
}
__device__ __forceinline__ void mma16816(float* c, const uint32_t* a,
                                         uint32_t b0, uint32_t b1) {
    asm volatile(
        "mma.sync.aligned.m16n8k16.row.col.f32.bf16.bf16.f32 "
        "{%0,%1,%2,%3}, {%4,%5,%6,%7}, {%8,%9}, {%0,%1,%2,%3};"
        : "+f"(c[0]), "+f"(c[1]), "+f"(c[2]), "+f"(c[3])
        : "r"(a[0]), "r"(a[1]), "r"(a[2]), "r"(a[3]), "r"(b0), "r"(b1));
}
// split x into bf16 hi/lo pairs, packed as bf16x2 words
__device__ __forceinline__ void split2(float x0, float x1,
                                       uint32_t& hi, uint32_t& lo) {
    __nv_bfloat162 h = __float22bfloat162_rn(make_float2(x0, x1));
    float2 hf = __bfloat1622float2(h);
    __nv_bfloat162 l = __float22bfloat162_rn(make_float2(x0 - hf.x, x1 - hf.y));
    hi = *(uint32_t*)&h;
    lo = *(uint32_t*)&l;
}

// ---------------- 1) BatchNorm statistics: partial sums ----------------------
__global__ void k_bn_partial(const float* __restrict__ H) {
    int t = threadIdx.x;
    int c = t & 63, rs = t >> 6;
    int row0 = blockIdx.x * 128;
    float s = 0.f, q = 0.f;
    const float* p = H + (size_t)(row0 + rs) * 64 + c;
    #pragma unroll 8
    for (int r = 0; r < 128; r += 4) {
        float v = p[(size_t)r * 64];
        s += v;
        q += v * v;
    }
    __shared__ float ss[256], sq[256];
    ss[t] = s; sq[t] = q;
    __syncthreads();
    if (t < 64) {
        s = ss[t] + ss[t + 64] + ss[t + 128] + ss[t + 192];
        q = sq[t] + sq[t + 64] + sq[t + 128] + sq[t + 192];
        g_psum[blockIdx.x * 64 + t] = s;
        g_psq[blockIdx.x * 64 + t] = q;
    }
}

// ---------------- 2) finalize BN + fold scale/shift; emit W'^T bf16 hi/lo ----
__global__ void k_finalize(const float* __restrict__ gamma,
                           const float* __restrict__ beta,
                           const float* __restrict__ W,
                           const float* __restrict__ bias) {
    int c = threadIdx.x;  // 0..63
    float s = 0.f, q = 0.f;
    for (int i = 0; i < 256; i++) {
        s += g_psum[i * 64 + c];
        q += g_psq[i * 64 + c];
    }
    float mean = s * (1.0f / 32768.0f);
    float var  = q * (1.0f / 32768.0f) - mean * mean;  // biased variance
    float sc = gamma[c] * rsqrtf(var + BN_EPS);
    float sh = beta[c] - mean * sc;
    __shared__ float ssc[64], ssh[64];
    ssc[c] = sc; ssh[c] = sh;
    __syncthreads();
    int o = c;  // this thread owns output column o
    float bp = bias[o];
    for (int cc = 0; cc < 64; cc++) {
        float w = W[cc * 64 + o];
        float wp = ssc[cc] * w;
        __nv_bfloat16 hi = __float2bfloat16_rn(wp);
        __nv_bfloat16 lo = __float2bfloat16_rn(wp - __bfloat162float(hi));
        g_Wt_hi[o * 64 + cc] = hi;   // transposed: [o][cc]
        g_Wt_lo[o * 64 + cc] = lo;
        bp += ssh[cc] * w;
    }
    g_bp[o] = bp;
}

// ---------------- 3) degree (row sums of A) ----------------------------------
__global__ void k_rowsum(const float* __restrict__ A) {
    int warp = threadIdx.x >> 5, lane = threadIdx.x & 31;
    int row = blockIdx.x * 8 + warp;
    const float4* p = (const float4*)A + (size_t)row * 256;
    float s = 0.f;
    #pragma unroll
    for (int it = 0; it < 8; it++) {
        float4 v = p[it * 32 + lane];
        s += (v.x + v.y) + (v.z + v.w);
    }
    #pragma unroll
    for (int off = 16; off; off >>= 1)
        s += __shfl_xor_sync(0xffffffffu, s, off);
    if (lane == 0) {
        g_sqd[row] = sqrtf(s);
        g_rsd[row] = rsqrtf(s);
    }
}

// ---------------- 4) HMMA computeX: X = H@W'^T + b'; Yt = (rsd*X)^T ----------
// Block: 128 rows, K=64. 8 warps, warp tile 32x32 (wm rows, wn cols).
#define WPAD 72   // bf16 row stride (144B): ldmatrix row bases hit distinct banks
#define CX_HH 0
#define CX_HL (128 * WPAD)
#define CX_WH (2 * 128 * WPAD)
#define CX_WL (2 * 128 * WPAD + 64 * WPAD)
#define CX_SMEM ((2 * 128 * WPAD + 2 * 64 * WPAD) * 2)   // 55296 B
#define YS_STRIDE 132

__global__ void __launch_bounds__(256) k_computeX(const float* __restrict__ H) {
    extern __shared__ __align__(16) char sm[];
    __nv_bfloat16* Hh = (__nv_bfloat16*)sm + CX_HH;
    __nv_bfloat16* Hl = (__nv_bfloat16*)sm + CX_HL;
    __nv_bfloat16* Wh = (__nv_bfloat16*)sm + CX_WH;
    __nv_bfloat16* Wl = (__nv_bfloat16*)sm + CX_WL;
    float* ys = (float*)sm;                 // reused after MMA: [64][132] fp32
    __shared__ float rs[128];
    __shared__ float bpS[64];

    int t = threadIdx.x, wid = t >> 5, lane = t & 31;
    int r0 = blockIdx.x * 128;
    int wm = wid & 3, wn = wid >> 2;

    if (t < 128) rs[t] = g_rsd[r0 + t];
    if (t < 64)  bpS[t] = g_bp[t];

    // H tile 128x64 fp32 -> bf16 hi/lo
    const float4* H4 = (const float4*)(H + (size_t)r0 * 64);
    #pragma unroll
    for (int i = 0; i < 8; i++) {
        int idx = t + i * 256;
        int row = idx >> 4, c4 = idx & 15;
        float4 v = __ldg(&H4[idx]);
        uint2 uh, ul;
        split2(v.x, v.y, uh.x, ul.x);
        split2(v.z, v.w, uh.y, ul.y);
        *(uint2*)&Hh[row * WPAD + c4 * 4] = uh;
        *(uint2*)&Hl[row * WPAD + c4 * 4] = ul;
    }
    // W'^T tiles (64x64 bf16, already split)
    #pragma unroll
    for (int i = 0; i < 2; i++) {
        int idx = t + i * 256;
        int row = idx >> 3, c8 = idx & 7;
        *(uint4*)&Wh[row * WPAD + c8 * 8] = ((const uint4*)g_Wt_hi)[idx];
        *(uint4*)&Wl[row * WPAD + c8 * 8] = ((const uint4*)g_Wt_lo)[idx];
    }
    __syncthreads();

    float c[2][4][4];
    #pragma unroll
    for (int mi = 0; mi < 2; mi++)
        #pragma unroll
        for (int ni = 0; ni < 4; ni++)
            #pragma unroll
            for (int r = 0; r < 4; r++) c[mi][ni][r] = 0.f;

    int qr = (lane & 7) + ((lane & 8) ? 8 : 0);
    int qk = (lane & 16) ? 8 : 0;

    #pragma unroll
    for (int kk = 0; kk < 4; kk++) {
        int k0 = kk * 16 + qk;
        uint32_t ah[2][4], al[2][4], bh[2][4], bl[2][4];
        #pragma unroll
        for (int mi = 0; mi < 2; mi++) {
            int r = (wm * 32 + mi * 16 + qr) * WPAD + k0;
            ldsm4(ah[mi], Hh + r);
            ldsm4(al[mi], Hl + r);
        }
        #pragma unroll
        for (int nj = 0; nj < 2; nj++) {
            int r = (wn * 32 + nj * 16 + qr) * WPAD + k0;
            ldsm4(bh[nj], Wh + r);
            ldsm4(bl[nj], Wl + r);
        }
        #pragma unroll
        for (int mi = 0; mi < 2; mi++)
            #pragma unroll
            for (int ni = 0; ni < 4; ni++) {
                int g = ni >> 1, s = ni & 1;
                mma16816(c[mi][ni], ah[mi], bh[g][s], bh[g][s + 2]);
                mma16816(c[mi][ni], ah[mi], bl[g][s], bl[g][s + 2]);
                mma16816(c[mi][ni], al[mi], bh[g][s], bh[g][s + 2]);
            }
    }
    __syncthreads();   // tiles dead; smem becomes ys

    // epilogue 1: X = acc + b' -> g_X (fp32); stage rsd*X transposed in ys
    {
        int rbase = wm * 32 + (lane >> 2);
        int cbase = wn * 32 + (lane & 3) * 2;
        #pragma unroll
        for (int mi = 0; mi < 2; mi++)
            #pragma unroll
            for (int half = 0; half < 2; half++) {
                int rl = rbase + mi * 16 + half * 8;
                float rsv = rs[rl];
                #pragma unroll
                for (int ni = 0; ni < 4; ni++) {
                    int col = cbase + ni * 8;
                    float x0 = c[mi][ni][half * 2 + 0] + bpS[col];
                    float x1 = c[mi][ni][half * 2 + 1] + bpS[col + 1];
                    *(float2*)(g_X + (size_t)(r0 + rl) * 64 + col) =
                        make_float2(x0, x1);
                    ys[col * YS_STRIDE + rl]       = x0 * rsv;
                    ys[(col + 1) * YS_STRIDE + rl] = x1 * rsv;
                }
            }
    }
    __syncthreads();

    // epilogue 2: Yt[b][n][l] bf16 hi/lo from ys
    {
        int n = t >> 2, part = t & 3;
        int b = r0 >> 10, lb = r0 & 1023;
        #pragma unroll
        for (int g = 0; g < 4; g++) {
            int l = part * 32 + g * 8;
            const float* p = ys + n * YS_STRIDE + l;
            uint4 vh, vl;
            split2(p[0], p[1], vh.x, vl.x);
            split2(p[2], p[3], vh.y, vl.y);
            split2(p[4], p[5], vh.z, vl.z);
            split2(p[6], p[7], vh.w, vl.w);
            size_t dst = ((size_t)(b * 64 + n) << 10) + lb + l;
            *(uint4*)(g_Yt_hi + dst) = vh;
            *(uint4*)(g_Yt_lo + dst) = vl;
        }
    }
}

// ---------------- 5) pipelined HMMA GEMM + epilogue --------------------------
// D[i,n] = sum_j A[i,j] * Y[j,n]   (bf16 hi/lo split, fp32 accum)
// out[i,n] = leaky( X[i,n] - sqd[i] * D[i,n] )
// NOTE: no min-blocks clause — ptxas must not spill (was capped at 128 regs
// by (256,2), forcing mainloop LDL/STL; ~160 regs live).
#define APAD 40          // bf16 row stride (80B)
#define ST_ELEMS 15360   // per-stage: A hi/lo 2*5120 + B hi/lo 2*2560
#define DYN_SMEM (2 * ST_ELEMS * 2)
#define NCHUNK 32

__global__ void __launch_bounds__(256) k_gemm_mma(const float* __restrict__ A,
                                                  float* __restrict__ out) {
    extern __shared__ __align__(16) __nv_bfloat16 smg[];

    int t = threadIdx.x, wid = t >> 5, lane = t & 31;
    int b = blockIdx.y, i0 = blockIdx.x * 128;
    int wm = wid & 3, wn = wid >> 2;

    float c[2][4][4];
    #pragma unroll
    for (int mi = 0; mi < 2; mi++)
        #pragma unroll
        for (int ni = 0; ni < 4; ni++)
            #pragma unroll
            for (int r = 0; r < 4; r++) c[mi][ni][r] = 0.f;

    const float4* A4 = (const float4*)(A + (size_t)b * NL * NL) + (size_t)i0 * 256;
    int lm = t >> 3, lk4 = t & 7;
    int ln = t >> 2, lk8 = t & 3;
    int qr = (lane & 7) + ((lane & 8) ? 8 : 0);
    int qk = (lane & 16) ? 8 : 0;

    float4 ra[4];
    uint4 rbh, rbl;

    auto LDG = [&](int ch) {
        int jc = ch * 32;
        #pragma unroll
        for (int it = 0; it < 4; it++)
            ra[it] = __ldg(&A4[(size_t)(lm + 32 * it) * 256 + (jc >> 2) + lk4]);
        size_t e = ((size_t)(b * 64 + ln) << 10) + jc + lk8 * 8;
        rbh = __ldg((const uint4*)(g_Yt_hi + e));
        rbl = __ldg((const uint4*)(g_Yt_lo + e));
    };
    auto STS = [&](int s) {
        __nv_bfloat16* Ah = smg + s * ST_ELEMS;
        __nv_bfloat16* Al = Ah + 5120;
        __nv_bfloat16* Bh = Ah + 10240;
        __nv_bfloat16* Bl = Ah + 12800;
        #pragma unroll
        for (int it = 0; it < 4; it++) {
            uint2 uh, ul;
            split2(ra[it].x, ra[it].y, uh.x, ul.x);
            split2(ra[it].z, ra[it].w, uh.y, ul.y);
            *(uint2*)&Ah[(lm + 32 * it) * APAD + lk4 * 4] = uh;
            *(uint2*)&Al[(lm + 32 * it) * APAD + lk4 * 4] = ul;
        }
        *(uint4*)&Bh[ln * APAD + lk8 * 8] = rbh;
        *(uint4*)&Bl[ln * APAD + lk8 * 8] = rbl;
    };

    LDG(0);
    STS(0);
    LDG(1);
    __syncthreads();

    #pragma unroll 1
    for (int ch = 0; ch < NCHUNK; ch++) {
        int cur = ch & 1;
        if (ch + 1 < NCHUNK) STS(cur ^ 1);
        if (ch + 2 < NCHUNK) LDG(ch + 2);

        const __nv_bfloat16* Ah = smg + cur * ST_ELEMS;
        const __nv_bfloat16* Al = Ah + 5120;
        const __nv_bfloat16* Bh = Ah + 10240;
        const __nv_bfloat16* Bl = Ah + 12800;
        #pragma unroll
        for (int kk = 0; kk < 2; kk++) {
            int k0 = kk * 16 + qk;
            uint32_t ah[2][4], al[2][4], bh[2][4], bl[2][4];
            #pragma unroll
            for (int mi = 0; mi < 2; mi++) {
                int r = (wm * 32 + mi * 16 + qr) * APAD + k0;
                ldsm4(ah[mi], Ah + r);
                ldsm4(al[mi], Al + r);
            }
            #pragma unroll
            for (int nj = 0; nj < 2; nj++) {
                int r = (wn * 32 + nj * 16 + qr) * APAD + k0;
                ldsm4(bh[nj], Bh + r);
                ldsm4(bl[nj], Bl + r);
            }
            #pragma unroll
            for (int mi = 0; mi < 2; mi++)
                #pragma unroll
                for (int ni = 0; ni < 4; ni++) {
                    int g = ni >> 1, s = ni & 1;
                    mma16816(c[mi][ni], ah[mi], bh[g][s], bh[g][s + 2]);
                    mma16816(c[mi][ni], ah[mi], bl[g][s], bl[g][s + 2]);
                    mma16816(c[mi][ni], al[mi], bh[g][s], bh[g][s + 2]);
                }
        }
        __syncthreads();
    }

    // epilogue: out = leaky(X - sqd * D)
    float* outb = out + (size_t)b * NL * 64;
    const float* Xb = g_X + (size_t)b * NL * 64;
    const float* sqd_b = g_sqd + (size_t)b * NL;
    int r0 = i0 + wm * 32 + (lane >> 2);
    int cbase = wn * 32 + (lane & 3) * 2;
    #pragma unroll
    for (int mi = 0; mi < 2; mi++) {
        #pragma unroll
        for (int half = 0; half < 2; half++) {
            int row = r0 + mi * 16 + half * 8;
            float sq = __ldg(sqd_b + row);
            #pragma unroll
            for (int ni = 0; ni < 4; ni++) {
                int col = cbase + ni * 8;
                float2 x = *(const float2*)(Xb + (size_t)row * 64 + col);
                float v0 = x.x - sq * c[mi][ni][half * 2 + 0];
                float v1 = x.y - sq * c[mi][ni][half * 2 + 1];
                v0 = v0 > 0.f ? v0 : 0.01f * v0;
                v1 = v1 > 0.f ? v1 : 0.01f * v1;
                *(float2*)(outb + (size_t)row * 64 + col) = make_float2(v0, v1);
            }
        }
    }
}

// ---------------- launch -----------------------------------------------------
extern "C" void kernel_launch(void* const* d_in, const int* in_sizes, int n_in,
                              void* d_out, int out_size) {
    (void)in_sizes; (void)n_in; (void)out_size;
    const float* H     = (const float*)d_in[0];
    const float* A     = (const float*)d_in[1];
    const float* gamma = (const float*)d_in[2];
    const float* beta  = (const float*)d_in[3];
    const float* W     = (const float*)d_in[4];
    const float* bias  = (const float*)d_in[5];
    float* out = (float*)d_out;

    cudaFuncSetAttribute(k_gemm_mma, cudaFuncAttributeMaxDynamicSharedMemorySize,
                         DYN_SMEM);
    cudaFuncSetAttribute(k_computeX, cudaFuncAttributeMaxDynamicSharedMemorySize,
                         CX_SMEM);

    k_bn_partial<<<256, 256>>>(H);
    k_rowsum<<<4096, 256>>>(A);
    k_finalize<<<1, 64>>>(gamma, beta, W, bias);
    k_computeX<<<256, 256, CX_SMEM>>>(H);
    k_gemm_mma<<<dim3(8, NB), 256, DYN_SMEM>>>(A, out);
}